// round 13
// baseline (speedup 1.0000x reference)
#include <cuda_runtime.h>
#include <cuda_bf16.h>

#define TT 512
#define LL 62
#define KK 64
#define GG 4
#define FULLM 0xffffffffu

__global__ void init_out_kernel(float* out) { out[0] = 0.0f; }

__device__ __forceinline__ __nv_bfloat162 ubf2(unsigned v) {
    __nv_bfloat162 r;
    *reinterpret_cast<unsigned*>(&r) = v;
    return r;
}

// dot for two owned indices: d_i = sum_{k=0}^{63} x[k] * Ei[k-pair].
// x bf16x2 pairs in smem (8 broadcast LDS.128), E pairs in registers.
__device__ __forceinline__ float2 dot2(const __nv_bfloat162* __restrict__ x_sh,
                                       const __nv_bfloat162* __restrict__ E0,
                                       const __nv_bfloat162* __restrict__ E1) {
    const uint4* up = reinterpret_cast<const uint4*>(x_sh);
    __nv_bfloat162 z = ubf2(0u);
    __nv_bfloat162 a0 = z, a1 = z, a2 = z, a3 = z;
    __nv_bfloat162 b0 = z, b1 = z, b2 = z, b3 = z;
    #pragma unroll
    for (int q = 0; q < 8; ++q) {
        const uint4 v = up[q];
        a0 = __hfma2(ubf2(v.x), E0[4 * q + 0], a0);
        b0 = __hfma2(ubf2(v.x), E1[4 * q + 0], b0);
        a1 = __hfma2(ubf2(v.y), E0[4 * q + 1], a1);
        b1 = __hfma2(ubf2(v.y), E1[4 * q + 1], b1);
        a2 = __hfma2(ubf2(v.z), E0[4 * q + 2], a2);
        b2 = __hfma2(ubf2(v.z), E1[4 * q + 2], b2);
        a3 = __hfma2(ubf2(v.w), E0[4 * q + 3], a3);
        b3 = __hfma2(ubf2(v.w), E1[4 * q + 3], b3);
    }
    const __nv_bfloat162 sa = __hadd2(__hadd2(a0, a1), __hadd2(a2, a3));
    const __nv_bfloat162 sb = __hadd2(__hadd2(b0, b1), __hadd2(b2, b3));
    const float2 fa = __bfloat1622float2(sa);
    const float2 fb = __bfloat1622float2(sb);
    return make_float2(fa.x + fa.y, fb.x + fb.y);
}

__global__ __launch_bounds__(64, 7) void crf_fb_solo_kernel(
    const float* __restrict__ pred,      // [B, T, L]
    const int*   __restrict__ ref,       // [B, T]
    const int*   __restrict__ seq_len,   // [B]
    const float* __restrict__ trans,     // [K, K]
    float* __restrict__ out)
{
    const int b    = blockIdx.x;
    const int tid  = threadIdx.x;
    const int wid  = tid >> 5;           // 0 = forward warp, 1 = backward warp
    const int lane = tid & 31;
    const int j0   = 2 * lane;           // two owned indices
    const int j1   = j0 + 1;
    const bool lab = (lane < 31);        // lane 31 owns states 62,63

    __shared__ __align__(16) __nv_bfloat162 xf[2][32];   // forward u buffers
    __shared__ __align__(16) __nv_bfloat162 xb[2][32];   // backward xs buffers
    __shared__ float uF[KK], wF[KK], cfb[2], redP[2], redG[2];

    const float* predb = pred + (size_t)b * TT * LL;
    const int*   refb  = ref  + (size_t)b * TT;
    const int    sl    = seq_len[b];
    const int    m     = sl >> 1;        // fwd steps; bwd steps = sl - m >= 1

    if (wid == 0) {
        // ============ forward: alpha_0 .. alpha_m, fully warp-local ============
        // E columns j0,j1 as k-pairs; rows 62,63 are exp(-10000) = 0.
        __nv_bfloat162 E0[32], E1[32];
        #pragma unroll
        for (int p = 0; p < 32; ++p) {
            E0[p] = __floats2bfloat162_rn(__expf(trans[(2 * p) * KK + j0]),
                                          __expf(trans[(2 * p + 1) * KK + j0]));
            E1[p] = __floats2bfloat162_rn(__expf(trans[(2 * p) * KK + j1]),
                                          __expf(trans[(2 * p + 1) * KK + j1]));
        }

        // u = exp(alpha - c), c = -1000: labels 1; start/end 0 (start's
        // outgoing E row is 0, its unit mass never propagates).
        float2 un = make_float2(lab ? 1.0f : 0.0f, lab ? 1.0f : 0.0f);
        float  c  = -1000.0f;
        xf[0][lane] = __floats2bfloat162_rn(un.x, un.y);
        int cur = 0;

        // eobs pipeline (fwd rows s-1 max m+GG-1 <= 259 < TT: no guard)
        float2 eA[GG], eB[GG];
        #pragma unroll
        for (int i = 0; i < GG; ++i) {
            const float2 o = lab ? __ldg((const float2*)&predb[i * LL + j0])
                                 : make_float2(-1000.0f, -1000.0f);
            eA[i] = make_float2(__expf(o.x), __expf(o.y));
        }

        int s = 1;
        while (s + GG <= m + 1) {
            #pragma unroll
            for (int i = 0; i < GG; ++i) {
                const int row = s + GG - 1 + i;
                const float2 o = lab ? __ldg((const float2*)&predb[row * LL + j0])
                                     : make_float2(-1000.0f, -1000.0f);
                eB[i] = make_float2(__expf(o.x), __expf(o.y));
            }
            #pragma unroll
            for (int i = 0; i < GG; ++i) {
                __syncwarp();
                float sc = 1.0f;
                if (i == 0 && s != 1) {          // deferred renorm / GG steps
                    const float u0 = __bfloat162float(xf[cur][0].x);
                    sc = __frcp_rn(u0);
                    c += __logf(u0);
                }
                const float2 d = dot2(xf[cur], E0, E1);
                un = make_float2(eA[i].x * sc * d.x, eA[i].y * sc * d.y);
                xf[cur ^ 1][lane] = __floats2bfloat162_rn(un.x, un.y);
                cur ^= 1;
            }
            #pragma unroll
            for (int i = 0; i < GG; ++i) eA[i] = eB[i];
            s += GG;
        }
        const int rem = m + 1 - s;               // 0..GG-1
        #pragma unroll
        for (int i = 0; i < GG - 1; ++i) {
            if (i >= rem) break;
            __syncwarp();
            float sc = 1.0f;
            if (i == 0 && s != 1) {
                const float u0 = __bfloat162float(xf[cur][0].x);
                sc = __frcp_rn(u0);
                c += __logf(u0);
            }
            const float2 d = dot2(xf[cur], E0, E1);
            un = make_float2(eA[i].x * sc * d.x, eA[i].y * sc * d.y);
            xf[cur ^ 1][lane] = __floats2bfloat162_rn(un.x, un.y);
            cur ^= 1;
        }
        uF[j0] = lab ? un.x : 0.0f;              // states 62,63 carry no mass
        uF[j1] = lab ? un.y : 0.0f;
        if (lane == 0) cfb[0] = c;
    } else {
        // ============ backward: beta_sl .. beta_m, fully warp-local ============
        // E rows j0,j1 as column-pairs.
        __nv_bfloat162 E0[32], E1[32];
        #pragma unroll
        for (int p = 0; p < 32; ++p) {
            E0[p] = __floats2bfloat162_rn(__expf(trans[j0 * KK + 2 * p]),
                                          __expf(trans[j0 * KK + 2 * p + 1]));
            E1[p] = __floats2bfloat162_rn(__expf(trans[j1 * KK + 2 * p]),
                                          __expf(trans[j1 * KK + 2 * p + 1]));
        }

        // analytic init: beta_sl[k] = trans[k][63] in e-domain (label boundary
        // terms are e^{-1000}-suppressed -> exactly 0 in fp32). Rows 62,63 of
        // trans are -10000 -> w = 0 there, permanently (their E rows are 0).
        float2 w = make_float2(__expf(trans[j0 * KK + 63]),
                               __expf(trans[j1 * KK + 63]));
        float  c = 0.0f;
        int  cur = 0;
        const int N = sl - m;                    // >= 1

        float2 eA[GG], eB[GG];
        #pragma unroll
        for (int i = 0; i < GG; ++i) {
            const int row = sl - 1 - i;
            if (lab && row >= 0) {
                const float2 o = __ldg((const float2*)&predb[row * LL + j0]);
                eA[i] = make_float2(__expf(o.x), __expf(o.y));
            } else eA[i] = make_float2(0.0f, 0.0f);
        }

        int q = 0;
        while (q + GG <= N) {
            #pragma unroll
            for (int i = 0; i < GG; ++i) {
                const int row = sl - 1 - (q + GG + i);
                if (lab && row >= 0) {
                    const float2 o = __ldg((const float2*)&predb[row * LL + j0]);
                    eB[i] = make_float2(__expf(o.x), __expf(o.y));
                } else eB[i] = make_float2(0.0f, 0.0f);
            }
            #pragma unroll
            for (int i = 0; i < GG; ++i) {
                float sc = 1.0f;
                if (i == 0 && q != 0) {          // probe = previous xs[0]
                    const float v0 = __bfloat162float(xb[cur ^ 1][0].x);
                    sc = __frcp_rn(v0);
                    c += __logf(v0);
                }
                xb[cur][lane] = __floats2bfloat162_rn(eA[i].x * sc * w.x,
                                                      eA[i].y * sc * w.y);
                __syncwarp();
                w = dot2(xb[cur], E0, E1);
                cur ^= 1;
            }
            #pragma unroll
            for (int i = 0; i < GG; ++i) eA[i] = eB[i];
            q += GG;
        }
        const int remb = N - q;                  // 0..GG-1
        #pragma unroll
        for (int i = 0; i < GG - 1; ++i) {
            if (i >= remb) break;
            float sc = 1.0f;
            if (i == 0 && q != 0) {
                const float v0 = __bfloat162float(xb[cur ^ 1][0].x);
                sc = __frcp_rn(v0);
                c += __logf(v0);
            }
            xb[cur][lane] = __floats2bfloat162_rn(eA[i].x * sc * w.x,
                                                  eA[i].y * sc * w.y);
            __syncwarp();
            w = dot2(xb[cur], E0, E1);
            cur ^= 1;
        }
        wF[j0] = w.x;                            // rows 62,63 are exactly 0
        wF[j1] = w.y;
        if (lane == 0) cfb[1] = c;
    }
    __syncthreads();

    // ---- combine: logZ = c_f + c_b + log( sum_k uF[k] * wF[k] ) ----
    float p = uF[tid] * wF[tid];
    #pragma unroll
    for (int off = 16; off; off >>= 1)
        p += __shfl_xor_sync(FULLM, p, off);
    if (lane == 0) redP[wid] = p;

    // ---- gold score, exact fp32, 64 threads ----
    float gold = 0.0f;
    for (int t = tid; t < sl; t += 64)
        gold += __ldg(&predb[t * LL + __ldg(&refb[t])]);
    for (int t = tid; t <= sl; t += 64) {
        const int from = (t == 0)  ? LL       : __ldg(&refb[t - 1]);
        const int to   = (t == sl) ? (LL + 1) : __ldg(&refb[t]);
        gold += __ldg(&trans[from * KK + to]);
    }
    #pragma unroll
    for (int off = 16; off; off >>= 1)
        gold += __shfl_xor_sync(FULLM, gold, off);
    if (lane == 0) redG[wid] = gold;
    __syncthreads();

    if (tid == 0) {
        const float S = redP[0] + redP[1];
        atomicAdd(out, cfb[0] + cfb[1] + __logf(S) - (redG[0] + redG[1]));
    }
}

extern "C" void kernel_launch(void* const* d_in, const int* in_sizes, int n_in,
                              void* d_out, int out_size)
{
    const float* pred    = (const float*)d_in[0];
    const int*   ref     = (const int*)d_in[1];
    const int*   seq_len = (const int*)d_in[2];
    const float* trans   = (const float*)d_in[3];
    float*       out     = (float*)d_out;

    const int B = in_sizes[2];   // 1024

    init_out_kernel<<<1, 1>>>(out);
    crf_fb_solo_kernel<<<B, 64>>>(pred, ref, seq_len, trans, out);
}

// round 15
// speedup vs baseline: 1.2457x; 1.2457x over previous
#include <cuda_runtime.h>
#include <cuda_bf16.h>

#define TT 512
#define LL 62
#define KK 64
#define GG 8
#define FULLM 0xffffffffu

__device__ int g_rank2batch[1024];

// Counting-sort batches by seq_len ascending; also zero the output scalar.
__global__ __launch_bounds__(1024) void sort_kernel(
    const int* __restrict__ seq_len, int B, float* __restrict__ out)
{
    __shared__ int scan_s[1024];
    __shared__ int cnt[1024];
    const int tid = threadIdx.x;

    if (tid == 0) out[0] = 0.0f;

    scan_s[tid] = 0;
    cnt[tid]    = 0;
    __syncthreads();

    int v = -1;
    if (tid < B && tid < 1024) {
        v = min(max(seq_len[tid], 0), 1023);
        atomicAdd(&scan_s[v], 1);
    }
    __syncthreads();

    // inclusive scan over 1024 bins (Hillis-Steele, in place)
    #pragma unroll
    for (int off = 1; off < 1024; off <<= 1) {
        int x = scan_s[tid];
        if (tid >= off) x += scan_s[tid - off];
        __syncthreads();
        scan_s[tid] = x;
        __syncthreads();
    }

    if (v >= 0) {
        const int base = (v > 0) ? scan_s[v - 1] : 0;
        const int r = base + atomicAdd(&cnt[v], 1);
        g_rank2batch[r] = tid;
    }
}

__device__ __forceinline__ __nv_bfloat162 u32_as_bf2(unsigned int v) {
    __nv_bfloat162 r;
    *reinterpret_cast<unsigned int*>(&r) = v;
    return r;
}

// dot_j = sum_{k=0}^{63} u[k] * E[k][j]; u bf16 in smem (broadcast LDS.128),
// E column j as bf16x2 register pairs. Rows 62,63 of E are exactly 0.
__device__ __forceinline__ float dot64h(const __nv_bfloat16* __restrict__ ubuf,
                                        const __nv_bfloat162* __restrict__ Epk) {
    const uint4* up = reinterpret_cast<const uint4*>(ubuf);
    __nv_bfloat162 z; *reinterpret_cast<unsigned int*>(&z) = 0u;
    __nv_bfloat162 a0 = z, a1 = z, a2 = z, a3 = z;
    #pragma unroll
    for (int q = 0; q < 8; ++q) {
        uint4 v = up[q];
        a0 = __hfma2(u32_as_bf2(v.x), Epk[4 * q + 0], a0);
        a1 = __hfma2(u32_as_bf2(v.y), Epk[4 * q + 1], a1);
        a2 = __hfma2(u32_as_bf2(v.z), Epk[4 * q + 2], a2);
        a3 = __hfma2(u32_as_bf2(v.w), Epk[4 * q + 3], a3);
    }
    __nv_bfloat162 s = __hadd2(__hadd2(a0, a1), __hadd2(a2, a3));
    float2 f = __bfloat1622float2(s);
    return f.x + f.y;
}

__global__ __launch_bounds__(KK) void crf_forward_kernel(
    const float* __restrict__ pred,      // [B, T, L]
    const int*   __restrict__ ref,       // [B, T]
    const int*   __restrict__ seq_len,   // [B]
    const float* __restrict__ trans,     // [K, K]
    float* __restrict__ out)             // scalar
{
    // snake-interleaved rank: SM class (bid % 148) gets one block from each
    // length septile, adjacent septiles reversed -> balanced per-SM work.
    int b;
    if (gridDim.x == 1024) {
        const int s = blockIdx.x % 148;
        const int g = blockIdx.x / 148;
        const int r = g * 148 + ((g & 1) ? (147 - s) : s);
        b = g_rank2batch[r];
    } else {
        b = blockIdx.x;
    }

    const int j    = threadIdx.x;
    const int lane = j & 31;
    const int wid  = j >> 5;

    __shared__ __align__(16) __nv_bfloat16 u_sh[2][KK];
    __shared__ float red[2];
    __shared__ float red2[2];

    const float* predb = pred + (size_t)b * TT * LL;
    const int*   refb  = ref  + (size_t)b * TT;
    const int    sl    = seq_len[b];

    // E column j as bf16x2 pairs. exp(-10000) -> 0 exactly (rows 62, 63).
    __nv_bfloat162 Epk[KK / 2];
    #pragma unroll
    for (int p = 0; p < KK / 2; ++p) {
        float e0 = __expf(trans[(2 * p + 0) * KK + j]);
        float e1 = __expf(trans[(2 * p + 1) * KK + j]);
        Epk[p] = __floats2bfloat162_rn(e0, e1);
    }

    // u_j = exp(alpha_j - c); init: labels 1.0 (alpha=-1000), start/end 0.
    float c = -1000.0f;
    u_sh[0][j] = __float2bfloat16((j < LL) ? 1.0f : 0.0f);
    int cur = 0;

    // eobs register pipeline, one 8-step group ahead (exp done at prefetch)
    const bool is_lab = (j < LL);
    float eobsA[GG], eobsB[GG];
    #pragma unroll
    for (int i = 0; i < GG; ++i)
        eobsA[i] = is_lab ? __expf(__ldg(&predb[i * LL + j])) : 0.0f;

    int s = 1;
    while (s + GG <= sl + 1) {               // steps s..s+7, all emission steps
        #pragma unroll
        for (int i = 0; i < GG; ++i) {       // prefetch steps s+8 .. s+15
            const int row = s + GG - 1 + i;
            eobsB[i] = (is_lab && row < TT) ? __expf(__ldg(&predb[row * LL + j]))
                                            : 0.0f;
        }
        #pragma unroll
        for (int i = 0; i < GG; ++i) {
            __syncthreads();
            float un = eobsA[i] * dot64h(u_sh[cur], Epk);
            if ((i & 3) == 3) {              // renorm every 4 steps by u[0]
                const float u0 = __bfloat162float(u_sh[cur][0]);
                c += __logf(u0);
                un = __fdividef(un, u0);
            }
            u_sh[cur ^ 1][j] = __float2bfloat16(un);
            cur ^= 1;
        }
        #pragma unroll
        for (int i = 0; i < GG; ++i) eobsA[i] = eobsB[i];
        s += GG;
    }

    const int rem = sl + 1 - s;              // 0..7 remaining emission steps
    #pragma unroll
    for (int i = 0; i < GG - 1; ++i) {
        if (i >= rem) break;
        __syncthreads();
        float un = eobsA[i] * dot64h(u_sh[cur], Epk);
        if ((i & 3) == 3) {
            const float u0 = __bfloat162float(u_sh[cur][0]);
            c += __logf(u0);
            un = __fdividef(un, u0);
        }
        u_sh[cur ^ 1][j] = __float2bfloat16(un);
        cur ^= 1;
    }
    __syncthreads();

    // ---- boundary step (step sl+1) in log domain, all 64 columns ----
    const float dB = dot64h(u_sh[cur], Epk);
    float obs_b;
    if (j < LL)
        obs_b = ((sl < TT) ? predb[sl * LL + j] : 0.0f) - 1000.0f;
    else
        obs_b = (j == LL) ? -1000.0f : 0.0f;
    const float alpha_fin = obs_b + c + __logf(dB);

    // ---- all-paths score: logsumexp over 64 final alphas (fp32) ----
    float v = alpha_fin;
    #pragma unroll
    for (int off = 16; off; off >>= 1)
        v = fmaxf(v, __shfl_xor_sync(FULLM, v, off));
    if (lane == 0) red[wid] = v;
    __syncthreads();
    const float M = fmaxf(red[0], red[1]);

    float e = __expf(alpha_fin - M);
    #pragma unroll
    for (int off = 16; off; off >>= 1)
        e += __shfl_xor_sync(FULLM, e, off);
    if (lane == 0) red2[wid] = e;
    __syncthreads();
    const float all_paths = M + __logf(red2[0] + red2[1]);

    // ---- gold (real) score (exact fp32) ----
    float gold = 0.0f;
    for (int t = j; t < sl; t += KK)
        gold += __ldg(&predb[t * LL + __ldg(&refb[t])]);
    for (int t = j; t <= sl; t += KK) {
        const int from = (t == 0)  ? LL       : __ldg(&refb[t - 1]);
        const int to   = (t == sl) ? (LL + 1) : __ldg(&refb[t]);
        gold += __ldg(&trans[from * KK + to]);
    }
    #pragma unroll
    for (int off = 16; off; off >>= 1)
        gold += __shfl_xor_sync(FULLM, gold, off);
    if (lane == 0) red[wid] = gold;
    __syncthreads();
    const float gold_total = red[0] + red[1];

    if (j == 0)
        atomicAdd(out, all_paths - gold_total);
}

extern "C" void kernel_launch(void* const* d_in, const int* in_sizes, int n_in,
                              void* d_out, int out_size)
{
    const float* pred    = (const float*)d_in[0];
    const int*   ref     = (const int*)d_in[1];
    const int*   seq_len = (const int*)d_in[2];
    const float* trans   = (const float*)d_in[3];
    float*       out     = (float*)d_out;

    const int B = in_sizes[2];   // 1024

    sort_kernel<<<1, 1024>>>(seq_len, B, out);
    crf_forward_kernel<<<B, KK>>>(pred, ref, seq_len, trans, out);
}